// round 4
// baseline (speedup 1.0000x reference)
#include <cuda_runtime.h>

#define NB     320
#define NHW    26
#define AREA   676          // 26*26
#define KPOS   3380         // 5*676
#define NBOX   50
#define NENT   (NB*NBOX)    // 16000
#define BS     16
#define CSZ    20
#define NMETA  20
#define DWROWS 64
#define DWCOLS 1024

// kernel A block layout
#define A_ENT   63                  // ceil(16000/256)
#define A_ENEW  20
#define A_BLOCKS (A_ENT + A_ENEW)
// kernel C block layout
#define MAIN_BPB 4                  // 1024 cells per block (256 thr * 4)
#define C_MAIN  (NB*MAIN_BPB)       // 1280
#define C_CORR  63                  // ceil(16000/256)
#define C_SAME  64                  // 65536 elems / (256*4)
#define C_DIFF  20
#define C_BLOCKS (C_MAIN + C_CORR + C_SAME + C_DIFF)

__constant__ float c_aw[5] = {1.3221f, 3.19275f, 5.05587f, 9.47112f, 11.2364f};
__constant__ float c_ah[5] = {1.73145f, 4.00944f, 8.09892f, 4.84053f, 10.0071f};

__device__ double g_acc;
__device__ int    g_done;
__device__ int    e_cell[NENT];     // global cell id (b*KPOS + ...) or -1
__device__ float4 g_bbox[NENT];
__device__ float  g_sarea[NENT];    // 0.375 * gw*gh
__device__ float  g_enews[NMETA*DWCOLS];
__device__ int    g_cnt[NMETA];

__device__ __forceinline__ float sigmoidf(float v){ return 1.f/(1.f+__expf(-v)); }

// ================= Kernel A: cheap entry geometry + class means + init =================
__global__ void __launch_bounds__(256) kA(const float* __restrict__ tgt,
                                          const float* __restrict__ dw,
                                          const int*   __restrict__ ids){
    int blk = blockIdx.x, tid = threadIdx.x;
    if(blk < A_ENT){
        if(blk == 0 && tid == 0){ g_acc = 0.0; g_done = 0; }
        int e = blk*256 + tid;
        if(e >= NENT) return;
        int b = e / NBOX;
        const float* g = tgt + e*5;
        float g1 = g[1];
        if(g1 == 0.0f){
            e_cell[e]  = -1;
            g_bbox[e]  = make_float4(3e9f, 3e9f, 3e9f, 3e9f);  // degenerate: never silences
            g_sarea[e] = 1.0f;
            return;
        }
        float gx = g1*26.f, gy = g[2]*26.f, gw = g[3]*26.f, gh = g[4]*26.f;
        g_bbox[e]  = make_float4(gx-0.5f*gw, gy-0.5f*gh, gx+0.5f*gw, gy+0.5f*gh);
        g_sarea[e] = 0.375f*gw*gh;

        int bn = 0; float best = -1.f;
        #pragma unroll
        for(int a=0; a<5; a++){
            float inter = fminf(gw, c_aw[a]) * fminf(gh, c_ah[a]);
            float iou = inter / (gw*gh + c_aw[a]*c_ah[a] - inter);
            if(iou > best){ best = iou; bn = a; }
        }
        int gi = (int)gx; gi = min(max(gi,0), NHW-1);
        int gj = (int)gy; gj = min(max(gj,0), NHW-1);
        e_cell[e] = b*KPOS + bn*AREA + gj*NHW + gi;
    } else {
        // per-class mean embeddings: one block per class
        int c = blk - A_ENT;
        __shared__ int sids[DWROWS];
        if(tid < DWROWS) sids[tid] = ids[tid];
        __syncthreads();
        int n = 0;
        #pragma unroll
        for(int r=0; r<DWROWS; r++) n += (sids[r] == c);
        if(tid == 0) g_cnt[c] = n;
        float inv = 1.f / (float)max(n, 1);
        for(int col = tid; col < DWCOLS; col += 256){
            float s = 0.f;
            #pragma unroll
            for(int r=0; r<DWROWS; r++){
                if(sids[r] == c) s += dw[r*DWCOLS + col];
            }
            g_enews[c*DWCOLS + col] = s * inv;
        }
    }
}

// ================= Kernel C: everything else, fused =================
__global__ void __launch_bounds__(256, 5) kC(const float* __restrict__ out,
                                             const float* __restrict__ tgt,
                                             const float* __restrict__ dw,
                                             const int*   __restrict__ ids,
                                             float* __restrict__ res){
    int blk = blockIdx.x, tid = threadIdx.x;
    float local = 0.f;

    if(blk < C_MAIN){
        // ---- default per-cell loss, 4 cells/thread ----
        int b     = blk >> 2;
        int chunk = blk & 3;
        int lc0   = chunk*1024 + tid*4;

        __shared__ float4 sb[NBOX];
        __shared__ float  sa[NBOX];
        if(tid < NBOX){
            sb[tid] = g_bbox[b*NBOX + tid];
            sa[tid] = g_sarea[b*NBOX + tid];
        }
        __syncthreads();

        if(lc0 < KPOS){
            int a  = lc0 / AREA;
            int r0 = lc0 - a*AREA;
            const float* p = out + ((b*5+a)*6)*AREA + r0;
            float4 xr = *(const float4*)(p);
            float4 yr = *(const float4*)(p +   AREA);
            float4 wr = *(const float4*)(p + 2*AREA);
            float4 hr = *(const float4*)(p + 3*AREA);
            float4 cr = *(const float4*)(p + 4*AREA);

            float px1[4], px2[4], py1[4], py2[4], pas[4], acc[4], cvh[4];
            float base = 0.f;
            {
                float xa[4] = {xr.x, xr.y, xr.z, xr.w};
                float ya[4] = {yr.x, yr.y, yr.z, yr.w};
                float wa[4] = {wr.x, wr.y, wr.z, wr.w};
                float ha[4] = {hr.x, hr.y, hr.z, hr.w};
                float ca[4] = {cr.x, cr.y, cr.z, cr.w};
                #pragma unroll
                for(int u=0; u<4; u++){
                    float xv = sigmoidf(xa[u]);
                    float yv = sigmoidf(ya[u]);
                    float wv = wa[u], hv = ha[u];
                    float cv = sigmoidf(ca[u]);
                    int r = r0 + u;
                    int j = r / NHW, i = r - j*NHW;
                    float pw = __expf(wv)*c_aw[a], ph = __expf(hv)*c_ah[a];
                    float px = xv + (float)i, py = yv + (float)j;
                    px1[u] = px - 0.5f*pw; px2[u] = px + 0.5f*pw;
                    py1[u] = py - 0.5f*ph; py2[u] = py + 0.5f*ph;
                    pas[u] = 0.375f*pw*ph;
                    acc[u] = -1e30f;
                    float dx = xv-0.5f, dy = yv-0.5f;
                    base += 0.5f*(dx*dx + dy*dy + wv*wv + hv*hv);
                    cvh[u] = 0.5f*cv*cv;
                }
            }
            #pragma unroll 10
            for(int t=0; t<NBOX; t++){
                float4 bb = sb[t];
                float s  = sa[t];
                #pragma unroll
                for(int u=0; u<4; u++){
                    float cw = fminf(px2[u], bb.z) - fmaxf(px1[u], bb.x);
                    cw = fmaxf(cw, 0.f);
                    float ch = fminf(py2[u], bb.w) - fmaxf(py1[u], bb.y);
                    acc[u] = fmaxf(acc[u], fmaf(cw, ch, -s));
                }
            }
            #pragma unroll
            for(int u=0; u<4; u++)
                base += (acc[u] > pas[u]) ? 0.f : cvh[u];
            local = base;
        }
    } else if(blk < C_MAIN + C_CORR){
        // ---- correction for matched (winner) entries ----
        __shared__ int s_cell[256 + NBOX];
        int e0 = (blk - C_MAIN)*256;
        {
            int e1 = e0 + tid;
            s_cell[tid] = (e1 < NENT) ? e_cell[e1] : -2;
            if(tid < NBOX){
                int e2 = e0 + 256 + tid;
                s_cell[256 + tid] = (e2 < NENT) ? e_cell[e2] : -2;
            }
        }
        __syncthreads();
        int e = e0 + tid;
        if(e < NENT){
            int cell = s_cell[tid];
            if(cell >= 0){
                int b = e / NBOX, t0 = e - b*NBOX;
                bool winner = true;
                #pragma unroll 7
                for(int t2 = t0+1; t2 < NBOX; t2++)
                    winner &= (s_cell[tid + (t2 - t0)] != cell);
                if(winner){
                    // recompute entry geometry from tgt
                    const float* g = tgt + e*5;
                    float gx = g[1]*26.f, gy = g[2]*26.f, gw = g[3]*26.f, gh = g[4]*26.f;
                    int bn = 0; float best = -1.f;
                    #pragma unroll
                    for(int aa=0; aa<5; aa++){
                        float inter = fminf(gw, c_aw[aa]) * fminf(gh, c_ah[aa]);
                        float iou = inter / (gw*gh + c_aw[aa]*c_ah[aa] - inter);
                        if(iou > best){ best = iou; bn = aa; }
                    }
                    int gi = (int)gx; gi = min(max(gi,0), NHW-1);
                    int gj = (int)gy; gj = min(max(gj,0), NHW-1);
                    float tx = gx - (float)gi, ty = gy - (float)gj;
                    float twv = logf(gw / c_aw[bn]), thv = logf(gh / c_ah[bn]);

                    int k = cell - b*KPOS;
                    int a = k / AREA, r = k - a*AREA;
                    const float* p = out + ((b*5+a)*6)*AREA + r;
                    float xv = sigmoidf(p[0]);
                    float yv = sigmoidf(p[AREA]);
                    float wv = p[2*AREA];
                    float hv = p[3*AREA];
                    float cvv = sigmoidf(p[4*AREA]);
                    int j = r / NHW, i = r - j*NHW;
                    float pw = __expf(wv)*c_aw[a], ph = __expf(hv)*c_ah[a];
                    float px = xv + (float)i, py = yv + (float)j;
                    // tconf: iou between gt box and pred box
                    float cwg = fminf(gx+0.5f*gw, px+0.5f*pw) - fmaxf(gx-0.5f*gw, px-0.5f*pw);
                    float chg = fminf(gy+0.5f*gh, py+0.5f*ph) - fmaxf(gy-0.5f*gh, py-0.5f*ph);
                    float interg = (cwg>0.f && chg>0.f) ? cwg*chg : 0.f;
                    float tconf = interg / (gw*gh + pw*ph - interg);
                    // recompute silent (same math as main)
                    float px1 = px-0.5f*pw, px2 = px+0.5f*pw;
                    float py1 = py-0.5f*ph, py2 = py+0.5f*ph;
                    float pas = 0.375f*pw*ph;
                    float acc = -1e30f;
                    for(int t=0; t<NBOX; t++){
                        float4 bb = g_bbox[b*NBOX + t];
                        float cw = fminf(px2, bb.z) - fmaxf(px1, bb.x);
                        cw = fmaxf(cw, 0.f);
                        float ch = fminf(py2, bb.w) - fmaxf(py1, bb.y);
                        acc = fmaxf(acc, fmaf(cw, ch, -g_sarea[b*NBOX + t]));
                    }
                    float cmd = (acc > pas) ? 0.f : 1.f;
                    float dx0 = xv-0.5f, dy0 = yv-0.5f;
                    float ldft = 0.5f*(dx0*dx0 + dy0*dy0 + wv*wv + hv*hv + cmd*cvv*cvv);
                    float dx = xv-tx, dy = yv-ty, dwv = wv-twv,
                          dh = hv-thv, dc = cvv-tconf;
                    float lmat = 0.5f*(dx*dx + dy*dy + dwv*dwv + dh*dh + 5.f*dc*dc);
                    // class loss for this cell: log-softmax over the 20-image group
                    int bsi = b / CSZ, cc = b - bsi*CSZ;
                    float v[CSZ]; float m = -3.4e38f;
                    #pragma unroll
                    for(int c2=0; c2<CSZ; c2++){
                        v[c2] = out[((bsi*CSZ+c2)*30 + a*6 + 5)*AREA + r];
                        m = fmaxf(m, v[c2]);
                    }
                    float s = 0.f;
                    #pragma unroll
                    for(int c2=0; c2<CSZ; c2++) s += __expf(v[c2]-m);
                    float lse = m + __logf(s);
                    local = lmat - ldft + (lse - v[cc]);
                }
            }
        }
    } else if(blk < C_MAIN + C_CORR + C_SAME){
        // ---- "same" loss, float4 per thread ----
        int idx4 = (blk - (C_MAIN + C_CORR))*256 + tid;
        int base = idx4*4;
        int r = base >> 10, c = base & 1023;
        float4 d  = *(const float4*)(dw + base);
        const float* en = g_enews + ids[r]*DWCOLS + c;
        float4 ev = *(const float4*)en;
        float a0 = d.x-ev.x, a1 = d.y-ev.y, a2 = d.z-ev.z, a3 = d.w-ev.w;
        local = a0*a0 + a1*a1 + a2*a2 + a3*a3;
    } else {
        // ---- pairwise distances + "different" loss ----
        int i = blk - (C_MAIN + C_CORR + C_SAME);
        float part[NMETA];
        #pragma unroll
        for(int j=0; j<NMETA; j++) part[j] = 0.f;
        for(int col=tid; col<DWCOLS; col+=256){
            float ei = g_enews[i*DWCOLS + col];
            #pragma unroll
            for(int j=0; j<NMETA; j++){
                float df = ei - g_enews[j*DWCOLS + col];
                part[j] += df*df;
            }
        }
        __shared__ float red2[256];
        __shared__ float dmat[NMETA];
        for(int j=0; j<NMETA; j++){
            red2[tid] = part[j]; __syncthreads();
            #pragma unroll
            for(int s=128; s>0; s>>=1){ if(tid<s) red2[tid]+=red2[tid+s]; __syncthreads(); }
            if(tid==0) dmat[j] = red2[0];
            __syncthreads();
        }
        if(tid == 0){
            bool pi = g_cnt[i] > 0;
            float dmin = 3.4e38f; bool any = false;
            for(int j=0; j<NMETA; j++){
                bool vp = pi && (g_cnt[j] > 0) && (j != i);
                if(vp){ any = true; dmin = fminf(dmin, dmat[j]); }
            }
            if(any) local = -dmin;
        }
    }

    // block reduce + global accumulate + last-block finalize
    __shared__ float red[256];
    red[tid] = local; __syncthreads();
    #pragma unroll
    for(int s=128; s>0; s>>=1){ if(tid<s) red[tid]+=red[tid+s]; __syncthreads(); }
    if(tid == 0){
        atomicAdd(&g_acc, (double)red[0]);
        __threadfence();
        int t = atomicAdd(&g_done, 1);
        if(t == C_BLOCKS - 1){
            res[0] = (float)g_acc;
        }
    }
}

extern "C" void kernel_launch(void* const* d_in, const int* in_sizes, int n_in,
                              void* d_out, int out_size){
    const float* outp = (const float*)d_in[0];   // (320,30,26,26)
    const float* tgt  = (const float*)d_in[1];   // (16,20,250) == (320,50,5)
    const float* dwp  = (const float*)d_in[2];   // (1,64,1024)
    const int*   ids  = (const int*)d_in[3];     // (64,)
    float* res = (float*)d_out;

    kA<<<A_BLOCKS, 256>>>(tgt, dwp, ids);
    kC<<<C_BLOCKS, 256>>>(outp, tgt, dwp, ids, res);
}

// round 6
// speedup vs baseline: 1.5467x; 1.5467x over previous
#include <cuda_runtime.h>
#include <cuda_fp16.h>

#define NB     320
#define NHW    26
#define AREA   676          // 26*26
#define KPOS   3380         // 5*676
#define NBOX   50
#define NENT   (NB*NBOX)    // 16000
#define BS     16
#define CSZ    20
#define NMETA  20
#define DWROWS 64
#define DWCOLS 1024

// kernel A block layout
#define A_ENT   63                  // ceil(16000/256)
#define A_ENEW  20
#define A_BLOCKS (A_ENT + A_ENEW)
// kernel C block layout (long-pole blocks first, mains after)
#define C_DIFF0 0
#define C_CORR0 (C_DIFF0 + 20)      // 20
#define C_SAME0 (C_CORR0 + 63)      // 83
#define C_MAIN0 (C_SAME0 + 64)      // 147
#define MAIN_BPB 4                  // 1024 cells per block (256 thr * 4)
#define C_BLOCKS (C_MAIN0 + NB*MAIN_BPB)   // 1427

__constant__ float c_aw[5] = {1.3221f, 3.19275f, 5.05587f, 9.47112f, 11.2364f};
__constant__ float c_ah[5] = {1.73145f, 4.00944f, 8.09892f, 4.84053f, 10.0071f};

__device__ double g_acc;
__device__ int    g_done;
__device__ int    e_cell[NENT];     // global cell id (b*KPOS + ...) or -1
__device__ uint4  g_bh[NENT];       // duplicated half2: bx1,bx2,by1,by2
__device__ unsigned g_nsh[NENT];    // duplicated half2 of -(0.375*gw*gh)
__device__ float  g_enews[NMETA*DWCOLS];
__device__ int    g_cnt[NMETA];

__device__ __forceinline__ float sigmoidf(float v){ return 1.f/(1.f+__expf(-v)); }
__device__ __forceinline__ unsigned duph(float v){
    return (unsigned)__half_as_ushort(__float2half_rn(v)) * 0x10001u;
}
union H2U { unsigned u; __half2 h; };
__device__ __forceinline__ __half2 u2h2(unsigned v){
    H2U c; c.u = v; return c.h;
}

// ================= Kernel A: cheap entry geometry (fp16 boxes) + class means + init =================
__global__ void __launch_bounds__(256) kA(const float* __restrict__ tgt,
                                          const float* __restrict__ dw,
                                          const int*   __restrict__ ids){
    int blk = blockIdx.x, tid = threadIdx.x;
    if(blk < A_ENT){
        if(blk == 0 && tid == 0){ g_acc = 0.0; g_done = 0; }
        int e = blk*256 + tid;
        if(e >= NENT) return;
        int b = e / NBOX;
        const float* g = tgt + e*5;
        float g1 = g[1];
        if(g1 == 0.0f){
            e_cell[e] = -1;
            unsigned far = duph(30000.f);
            g_bh[e]  = make_uint4(far, far, far, far);   // degenerate: never silences
            g_nsh[e] = duph(-1.f);
            return;
        }
        float gx = g1*26.f, gy = g[2]*26.f, gw = g[3]*26.f, gh = g[4]*26.f;
        g_bh[e]  = make_uint4(duph(gx-0.5f*gw), duph(gx+0.5f*gw),
                              duph(gy-0.5f*gh), duph(gy+0.5f*gh));
        g_nsh[e] = duph(-0.375f*gw*gh);

        int bn = 0; float best = -1.f;
        #pragma unroll
        for(int a=0; a<5; a++){
            float inter = fminf(gw, c_aw[a]) * fminf(gh, c_ah[a]);
            float iou = inter / (gw*gh + c_aw[a]*c_ah[a] - inter);
            if(iou > best){ best = iou; bn = a; }
        }
        int gi = (int)gx; gi = min(max(gi,0), NHW-1);
        int gj = (int)gy; gj = min(max(gj,0), NHW-1);
        e_cell[e] = b*KPOS + bn*AREA + gj*NHW + gi;
    } else {
        // per-class mean embeddings: one block per class
        int c = blk - A_ENT;
        __shared__ int sids[DWROWS];
        if(tid < DWROWS) sids[tid] = ids[tid];
        __syncthreads();
        int n = 0;
        #pragma unroll
        for(int r=0; r<DWROWS; r++) n += (sids[r] == c);
        if(tid == 0) g_cnt[c] = n;
        float inv = 1.f / (float)max(n, 1);
        for(int col = tid; col < DWCOLS; col += 256){
            float s = 0.f;
            #pragma unroll
            for(int r=0; r<DWROWS; r++){
                if(sids[r] == c) s += dw[r*DWCOLS + col];
            }
            g_enews[c*DWCOLS + col] = s * inv;
        }
    }
}

// identical-bits silence accumulator for one duplicated cell (used by corr)
__device__ __forceinline__ float silent_acc_corr(float px1, float px2, float py1, float py2, int b){
    __half2 hx1 = __float2half2_rn(px1), hx2 = __float2half2_rn(px2);
    __half2 hy1 = __float2half2_rn(py1), hy2 = __float2half2_rn(py2);
    __half2 zero2 = __float2half2_rn(0.f);
    __half2 acc = u2h2(0xFC00FC00u);   // -inf,-inf
    const uint4* bb = g_bh + b*NBOX;
    const unsigned* ns = g_nsh + b*NBOX;
    for(int t=0; t<NBOX; t++){
        uint4 B = bb[t];
        __half2 cw = __hsub2(__hmin2(hx2, u2h2(B.y)), __hmax2(hx1, u2h2(B.x)));
        cw = __hmax2(cw, zero2);
        __half2 ch = __hsub2(__hmin2(hy2, u2h2(B.w)), __hmax2(hy1, u2h2(B.z)));
        acc = __hmax2(acc, __hfma2(cw, ch, u2h2(ns[t])));
    }
    return __low2float(acc);
}

// ================= Kernel C: everything else, fused =================
__global__ void __launch_bounds__(256) kC(const float* __restrict__ out,
                                          const float* __restrict__ tgt,
                                          const float* __restrict__ dw,
                                          const int*   __restrict__ ids,
                                          float* __restrict__ res){
    int blk = blockIdx.x, tid = threadIdx.x;
    float local = 0.f;

    if(blk >= C_MAIN0){
        // ---- default per-cell loss, 4 cells/thread, fp16x2 silence test ----
        int mb    = blk - C_MAIN0;
        int b     = mb >> 2;
        int chunk = mb & 3;
        int lc0   = chunk*1024 + tid*4;

        __shared__ uint4    sb[NBOX];
        __shared__ unsigned sns[NBOX];
        if(tid < NBOX){
            sb[tid]  = g_bh[b*NBOX + tid];
            sns[tid] = g_nsh[b*NBOX + tid];
        }
        __syncthreads();

        if(lc0 < KPOS){
            int a  = lc0 / AREA;
            int r0 = lc0 - a*AREA;
            const float* p = out + ((b*5+a)*6)*AREA + r0;
            float4 xr = *(const float4*)(p);
            float4 yr = *(const float4*)(p +   AREA);
            float4 wr = *(const float4*)(p + 2*AREA);
            float4 hr = *(const float4*)(p + 3*AREA);
            float4 cr = *(const float4*)(p + 4*AREA);

            float pas[4], cvh[4];
            __half2 hx1[2], hx2[2], hy1[2], hy2[2];
            float base = 0.f;
            {
                float xa[4] = {xr.x, xr.y, xr.z, xr.w};
                float ya[4] = {yr.x, yr.y, yr.z, yr.w};
                float wa[4] = {wr.x, wr.y, wr.z, wr.w};
                float ha[4] = {hr.x, hr.y, hr.z, hr.w};
                float ca[4] = {cr.x, cr.y, cr.z, cr.w};
                float px1[4], px2[4], py1[4], py2[4];
                #pragma unroll
                for(int u=0; u<4; u++){
                    float xv = sigmoidf(xa[u]);
                    float yv = sigmoidf(ya[u]);
                    float wv = wa[u], hv = ha[u];
                    float cv = sigmoidf(ca[u]);
                    int r = r0 + u;
                    int j = r / NHW, i = r - j*NHW;
                    float pw = __expf(wv)*c_aw[a], ph = __expf(hv)*c_ah[a];
                    float px = xv + (float)i, py = yv + (float)j;
                    px1[u] = px - 0.5f*pw; px2[u] = px + 0.5f*pw;
                    py1[u] = py - 0.5f*ph; py2[u] = py + 0.5f*ph;
                    pas[u] = 0.375f*pw*ph;
                    float dx = xv-0.5f, dy = yv-0.5f;
                    base += 0.5f*(dx*dx + dy*dy + wv*wv + hv*hv);
                    cvh[u] = 0.5f*cv*cv;
                }
                hx1[0] = __floats2half2_rn(px1[0], px1[1]); hx1[1] = __floats2half2_rn(px1[2], px1[3]);
                hx2[0] = __floats2half2_rn(px2[0], px2[1]); hx2[1] = __floats2half2_rn(px2[2], px2[3]);
                hy1[0] = __floats2half2_rn(py1[0], py1[1]); hy1[1] = __floats2half2_rn(py1[2], py1[3]);
                hy2[0] = __floats2half2_rn(py2[0], py2[1]); hy2[1] = __floats2half2_rn(py2[2], py2[3]);
            }
            __half2 zero2 = __float2half2_rn(0.f);
            __half2 acc0 = u2h2(0xFC00FC00u), acc1 = u2h2(0xFC00FC00u);
            #pragma unroll 10
            for(int t=0; t<NBOX; t++){
                uint4 B = sb[t];
                __half2 ns  = u2h2(sns[t]);
                __half2 bx1 = u2h2(B.x), bx2 = u2h2(B.y), by1 = u2h2(B.z), by2 = u2h2(B.w);
                __half2 cw0 = __hsub2(__hmin2(hx2[0], bx2), __hmax2(hx1[0], bx1));
                cw0 = __hmax2(cw0, zero2);
                __half2 ch0 = __hsub2(__hmin2(hy2[0], by2), __hmax2(hy1[0], by1));
                acc0 = __hmax2(acc0, __hfma2(cw0, ch0, ns));
                __half2 cw1 = __hsub2(__hmin2(hx2[1], bx2), __hmax2(hx1[1], bx1));
                cw1 = __hmax2(cw1, zero2);
                __half2 ch1 = __hsub2(__hmin2(hy2[1], by2), __hmax2(hy1[1], by1));
                acc1 = __hmax2(acc1, __hfma2(cw1, ch1, ns));
            }
            float a0 = __low2float(acc0), a1 = __high2float(acc0);
            float a2 = __low2float(acc1), a3 = __high2float(acc1);
            base += (a0 > pas[0]) ? 0.f : cvh[0];
            base += (a1 > pas[1]) ? 0.f : cvh[1];
            base += (a2 > pas[2]) ? 0.f : cvh[2];
            base += (a3 > pas[3]) ? 0.f : cvh[3];
            local = base;
        }
    } else if(blk >= C_SAME0){
        // ---- "same" loss, float4 per thread ----
        int idx4 = (blk - C_SAME0)*256 + tid;
        int base = idx4*4;
        int r = base >> 10, c = base & 1023;
        float4 d  = *(const float4*)(dw + base);
        const float* en = g_enews + ids[r]*DWCOLS + c;
        float4 ev = *(const float4*)en;
        float a0 = d.x-ev.x, a1 = d.y-ev.y, a2 = d.z-ev.z, a3 = d.w-ev.w;
        local = a0*a0 + a1*a1 + a2*a2 + a3*a3;
    } else if(blk >= C_CORR0){
        // ---- correction for matched (winner) entries ----
        __shared__ int s_cell[256 + NBOX];
        int e0 = (blk - C_CORR0)*256;
        {
            int e1 = e0 + tid;
            s_cell[tid] = (e1 < NENT) ? e_cell[e1] : -2;
            if(tid < NBOX){
                int e2 = e0 + 256 + tid;
                s_cell[256 + tid] = (e2 < NENT) ? e_cell[e2] : -2;
            }
        }
        __syncthreads();
        int e = e0 + tid;
        if(e < NENT){
            int cell = s_cell[tid];
            if(cell >= 0){
                int b = e / NBOX, t0 = e - b*NBOX;
                bool winner = true;
                #pragma unroll 7
                for(int t2 = t0+1; t2 < NBOX; t2++)
                    winner &= (s_cell[tid + (t2 - t0)] != cell);
                if(winner){
                    // recompute entry geometry from tgt (fp32, exact)
                    const float* g = tgt + e*5;
                    float gx = g[1]*26.f, gy = g[2]*26.f, gw = g[3]*26.f, gh = g[4]*26.f;
                    int bn = 0; float best = -1.f;
                    #pragma unroll
                    for(int aa=0; aa<5; aa++){
                        float inter = fminf(gw, c_aw[aa]) * fminf(gh, c_ah[aa]);
                        float iou = inter / (gw*gh + c_aw[aa]*c_ah[aa] - inter);
                        if(iou > best){ best = iou; bn = aa; }
                    }
                    int gi = (int)gx; gi = min(max(gi,0), NHW-1);
                    int gj = (int)gy; gj = min(max(gj,0), NHW-1);
                    float tx = gx - (float)gi, ty = gy - (float)gj;
                    float twv = logf(gw / c_aw[bn]), thv = logf(gh / c_ah[bn]);

                    int k = cell - b*KPOS;
                    int a = k / AREA, r = k - a*AREA;
                    const float* p = out + ((b*5+a)*6)*AREA + r;
                    float xv = sigmoidf(p[0]);
                    float yv = sigmoidf(p[AREA]);
                    float wv = p[2*AREA];
                    float hv = p[3*AREA];
                    float cvv = sigmoidf(p[4*AREA]);
                    int j = r / NHW, i = r - j*NHW;
                    float pw = __expf(wv)*c_aw[a], ph = __expf(hv)*c_ah[a];
                    float px = xv + (float)i, py = yv + (float)j;
                    // tconf: iou between gt box and pred box (fp32, exact)
                    float cwg = fminf(gx+0.5f*gw, px+0.5f*pw) - fmaxf(gx-0.5f*gw, px-0.5f*pw);
                    float chg = fminf(gy+0.5f*gh, py+0.5f*ph) - fmaxf(gy-0.5f*gh, py-0.5f*ph);
                    float interg = (cwg>0.f && chg>0.f) ? cwg*chg : 0.f;
                    float tconf = interg / (gw*gh + pw*ph - interg);
                    // silent: IDENTICAL fp16 path as main -> exact cancellation
                    float px1 = px-0.5f*pw, px2 = px+0.5f*pw;
                    float py1 = py-0.5f*ph, py2 = py+0.5f*ph;
                    float pas = 0.375f*pw*ph;
                    float acc = silent_acc_corr(px1, px2, py1, py2, b);
                    float cmd = (acc > pas) ? 0.f : 1.f;
                    float dx0 = xv-0.5f, dy0 = yv-0.5f;
                    float ldft = 0.5f*(dx0*dx0 + dy0*dy0 + wv*wv + hv*hv + cmd*cvv*cvv);
                    float dx = xv-tx, dy = yv-ty, dwv = wv-twv,
                          dh = hv-thv, dc = cvv-tconf;
                    float lmat = 0.5f*(dx*dx + dy*dy + dwv*dwv + dh*dh + 5.f*dc*dc);
                    // class loss for this cell: log-softmax over the 20-image group
                    int bsi = b / CSZ, cc = b - bsi*CSZ;
                    float v[CSZ]; float m = -3.4e38f;
                    #pragma unroll
                    for(int c2=0; c2<CSZ; c2++){
                        v[c2] = out[((bsi*CSZ+c2)*30 + a*6 + 5)*AREA + r];
                        m = fmaxf(m, v[c2]);
                    }
                    float s = 0.f;
                    #pragma unroll
                    for(int c2=0; c2<CSZ; c2++) s += __expf(v[c2]-m);
                    float lse = m + __logf(s);
                    local = lmat - ldft + (lse - v[cc]);
                }
            }
        }
    } else {
        // ---- pairwise distances + "different" loss (warp-reduce, no serial block reductions) ----
        int i = blk;
        float part[NMETA];
        #pragma unroll
        for(int j=0; j<NMETA; j++) part[j] = 0.f;
        for(int col=tid; col<DWCOLS; col+=256){
            float ei = g_enews[i*DWCOLS + col];
            #pragma unroll
            for(int j=0; j<NMETA; j++){
                float df = ei - g_enews[j*DWCOLS + col];
                part[j] += df*df;
            }
        }
        __shared__ float dmat[NMETA];
        if(tid < NMETA) dmat[tid] = 0.f;
        __syncthreads();
        int lane = tid & 31;
        #pragma unroll
        for(int j=0; j<NMETA; j++){
            float v = part[j];
            #pragma unroll
            for(int o=16; o>0; o>>=1) v += __shfl_xor_sync(0xffffffffu, v, o);
            if(lane == 0) atomicAdd(&dmat[j], v);
        }
        __syncthreads();
        if(tid == 0){
            bool pi = g_cnt[i] > 0;
            float dmin = 3.4e38f; bool any = false;
            for(int j=0; j<NMETA; j++){
                bool vp = pi && (g_cnt[j] > 0) && (j != i);
                if(vp){ any = true; dmin = fminf(dmin, dmat[j]); }
            }
            if(any) local = -dmin;
        }
    }

    // block reduce + global accumulate + last-block finalize
    __shared__ float red[256];
    red[tid] = local; __syncthreads();
    #pragma unroll
    for(int s=128; s>0; s>>=1){ if(tid<s) red[tid]+=red[tid+s]; __syncthreads(); }
    if(tid == 0){
        atomicAdd(&g_acc, (double)red[0]);
        __threadfence();
        int t = atomicAdd(&g_done, 1);
        if(t == C_BLOCKS - 1){
            res[0] = (float)g_acc;
        }
    }
}

extern "C" void kernel_launch(void* const* d_in, const int* in_sizes, int n_in,
                              void* d_out, int out_size){
    const float* outp = (const float*)d_in[0];   // (320,30,26,26)
    const float* tgt  = (const float*)d_in[1];   // (16,20,250) == (320,50,5)
    const float* dwp  = (const float*)d_in[2];   // (1,64,1024)
    const int*   ids  = (const int*)d_in[3];     // (64,)
    float* res = (float*)d_out;

    kA<<<A_BLOCKS, 256>>>(tgt, dwp, ids);
    kC<<<C_BLOCKS, 256>>>(outp, tgt, dwp, ids, res);
}